// round 16
// baseline (speedup 1.0000x reference)
#include <cuda_runtime.h>
#include <math.h>
#include <cstdint>

#define B_ 4
#define S_ 2048
#define D_ 1024
#define H_ 16
#define HD_ 64
#define FF_ 4096
#define ROWS_ (B_ * S_)   // 8192
#define QKVN 3072

// ---------------- scratch (device globals; no allocation) ----------------
__device__ float g_ln[ROWS_ * D_];
__device__ float g_qkv[(size_t)ROWS_ * QKVN];
__device__ float g_attn[ROWS_ * D_];
__device__ float g_h[(size_t)ROWS_ * FF_];
__device__ float g_wqkvT[QKVN * D_];   // transposed+rounded [n][k]
__device__ float g_woT[D_ * D_];
__device__ float g_w1T[FF_ * D_];
__device__ float g_w2T[D_ * FF_];

// ---------------- helpers ----------------
__device__ __forceinline__ uint32_t smem_u32(const void* p) {
    uint32_t a;
    asm("{ .reg .u64 t; cvta.to.shared.u64 t, %1; cvt.u32.u64 %0, t; }" : "=r"(a) : "l"(p));
    return a;
}
#define CP_ASYNC16(dst, src) \
    asm volatile("cp.async.cg.shared.global [%0], [%1], 16;" :: "r"(dst), "l"(src))
#define CP_COMMIT() asm volatile("cp.async.commit_group;" ::: "memory")
#define CP_WAIT(n)  asm volatile("cp.async.wait_group %0;" :: "n"(n) : "memory")
#define LDSM4(r0, r1, r2, r3, addr) \
    asm volatile("ldmatrix.sync.aligned.m8n8.x4.shared.b16 {%0,%1,%2,%3}, [%4];" \
                 : "=r"(r0), "=r"(r1), "=r"(r2), "=r"(r3) : "r"(addr))

__device__ __forceinline__ unsigned f2tf32(float f) {
    unsigned u;
    asm("cvt.rna.tf32.f32 %0, %1;" : "=r"(u) : "f"(f));
    return u;
}
__device__ __forceinline__ float f2tf32f(float f) { return __uint_as_float(f2tf32(f)); }

__device__ __forceinline__ void mma_tf32(float c[4], unsigned a0, unsigned a1,
                                         unsigned a2, unsigned a3,
                                         unsigned b0, unsigned b1) {
    asm volatile(
        "mma.sync.aligned.m16n8k8.row.col.f32.tf32.tf32.f32 "
        "{%0,%1,%2,%3}, {%4,%5,%6,%7}, {%8,%9}, {%0,%1,%2,%3};"
        : "+f"(c[0]), "+f"(c[1]), "+f"(c[2]), "+f"(c[3])
        : "r"(a0), "r"(a1), "r"(a2), "r"(a3), "r"(b0), "r"(b1));
}

// ---------------- weight transpose + tf32 round: out[n][k] = rna(in[k][n]) ----------------
__global__ void tround(const float* __restrict__ in, float* __restrict__ out,
                       int K, int N) {
    __shared__ float t[32][33];
    int n0 = blockIdx.x * 32, k0 = blockIdx.y * 32;
    int tx = threadIdx.x, ty = threadIdx.y;    // 32 x 8
#pragma unroll
    for (int i = 0; i < 4; i++)
        t[ty + 8 * i][tx] = in[(size_t)(k0 + ty + 8 * i) * N + n0 + tx];
    __syncthreads();
#pragma unroll
    for (int i = 0; i < 4; i++)
        out[(size_t)(n0 + ty + 8 * i) * K + k0 + tx] = f2tf32f(t[tx][ty + 8 * i]);
}

// ---------------- LayerNorm (output rounded to tf32) ----------------
__global__ void ln_kernel(const float* __restrict__ x, const float* __restrict__ g,
                          const float* __restrict__ b, float* __restrict__ y) {
    int row = blockIdx.x;
    int tid = threadIdx.x;
    const float4* xr = (const float4*)(x + (size_t)row * D_);
    float4 v = xr[tid];
    float s  = v.x + v.y + v.z + v.w;
    float ss = fmaf(v.x, v.x, fmaf(v.y, v.y, fmaf(v.z, v.z, v.w * v.w)));
#pragma unroll
    for (int o = 16; o > 0; o >>= 1) {
        s  += __shfl_xor_sync(0xffffffffu, s,  o);
        ss += __shfl_xor_sync(0xffffffffu, ss, o);
    }
    __shared__ float smS[8], smSS[8];
    __shared__ float mean_s, rstd_s;
    int wid = tid >> 5, lane = tid & 31;
    if (lane == 0) { smS[wid] = s; smSS[wid] = ss; }
    __syncthreads();
    if (tid == 0) {
        float S = 0.f, SQ = 0.f;
#pragma unroll
        for (int i = 0; i < 8; i++) { S += smS[i]; SQ += smSS[i]; }
        float m = S * (1.0f / D_);
        float var = SQ * (1.0f / D_) - m * m;
        mean_s = m;
        rstd_s = rsqrtf(var + 1e-5f);
    }
    __syncthreads();
    float m = mean_s, rs = rstd_s;
    float4 g4 = ((const float4*)g)[tid];
    float4 b4 = ((const float4*)b)[tid];
    float4 o;
    o.x = f2tf32f((v.x - m) * rs * g4.x + b4.x);
    o.y = f2tf32f((v.y - m) * rs * g4.y + b4.y);
    o.z = f2tf32f((v.z - m) * rs * g4.z + b4.z);
    o.w = f2tf32f((v.w - m) * rs * g4.w + b4.w);
    ((float4*)(y + (size_t)row * D_))[tid] = o;
}

// ---------------- TF32 tensor GEMM: 128x256 CTA tile, 64x64 warp tile ----------------
// C[M,N] = A[M,K] @ Wt^T, Wt is [N][K]. 8 warps (2m x 4n), 1 CTA/SM.
#define STAGES 3
#define KS 32
#define ASTRIDE 36
#define A_STG (128 * ASTRIDE)                   // 4608 floats
#define B_STG (256 * ASTRIDE)                   // 9216 floats
#define STG_FLOATS (A_STG + B_STG)              // 13824
#define STG_BYTES (STG_FLOATS * 4)              // 55296
#define TG_SMEM_BYTES (STAGES * STG_BYTES)      // 165888

template <bool BIAS, bool GELU, bool RES, bool ROUND>
__global__ void __launch_bounds__(256)
tgemm(const float* __restrict__ A, const float* __restrict__ Wt,
      float* __restrict__ C, const float* __restrict__ bias,
      const float* __restrict__ resid, int M, int N, int K) {
    extern __shared__ float sm[];
    int tid  = threadIdx.x;
    int lane = tid & 31;
    int wid  = tid >> 5;
    int wm   = wid >> 2;          // 0..1
    int wn   = wid & 3;           // 0..3
    int bm   = blockIdx.y * 128;
    int bn   = blockIdx.x * 256;
    int r    = lane >> 2;
    int c    = lane & 3;

    const int KT = K / KS;
    uint32_t sbase = smem_u32(sm);

    int l8  = lane & 7;
    int lhi = (lane >> 3) & 1;
    int lc4 = (lane >> 4) & 1;
    uint32_t aAddr[4], bAddr[4];
#pragma unroll
    for (int mt = 0; mt < 4; mt++) {
        int row = wm * 64 + mt * 16 + l8 + lhi * 8;
        aAddr[mt] = sbase + (uint32_t)(row * ASTRIDE + lc4 * 4) * 4;
    }
#pragma unroll
    for (int p = 0; p < 4; p++) {
        int row = wn * 64 + p * 16 + l8 + lhi * 8;
        bAddr[p] = sbase + (uint32_t)(A_STG + row * ASTRIDE + lc4 * 4) * 4;
    }

    auto load_stage = [&](int kt, int s) {
        float* sa = sm + s * STG_FLOATS;
        float* sb = sa + A_STG;
        const float* Ag = A  + (size_t)bm * K + kt * KS;
        const float* Bg = Wt + (size_t)bn * K + kt * KS;
#pragma unroll
        for (int i = 0; i < 4; i++) {
            int j = tid + 256 * i;          // 0..1023
            int row = j >> 3, ch = j & 7;
            CP_ASYNC16(smem_u32(&sa[row * ASTRIDE + ch * 4]),
                       Ag + (size_t)row * K + ch * 4);
        }
#pragma unroll
        for (int i = 0; i < 8; i++) {
            int j = tid + 256 * i;          // 0..2047
            int row = j >> 3, ch = j & 7;
            CP_ASYNC16(smem_u32(&sb[row * ASTRIDE + ch * 4]),
                       Bg + (size_t)row * K + ch * 4);
        }
    };

    float acc[4][8][4];
#pragma unroll
    for (int i = 0; i < 4; i++)
#pragma unroll
        for (int j = 0; j < 8; j++)
#pragma unroll
            for (int t = 0; t < 4; t++) acc[i][j][t] = 0.f;

#pragma unroll
    for (int s = 0; s < STAGES - 1; s++) {
        load_stage(s, s);
        CP_COMMIT();
    }
    CP_WAIT(STAGES - 2);
    __syncthreads();

    unsigned af[4][4], bf[8][2];
    auto frag_load = [&](int s, int ks) {
        uint32_t off = (uint32_t)s * STG_BYTES + (uint32_t)ks * 32;
#pragma unroll
        for (int mt = 0; mt < 4; mt++)
            LDSM4(af[mt][0], af[mt][1], af[mt][2], af[mt][3], aAddr[mt] + off);
        // x4 address-order: m0=(tile 2p,k0-3), m1=(tile 2p+1,k0-3), m2=(tile 2p,k4-7), m3=(tile 2p+1,k4-7)
#pragma unroll
        for (int p = 0; p < 4; p++)
            LDSM4(bf[2 * p][0], bf[2 * p + 1][0], bf[2 * p][1], bf[2 * p + 1][1],
                  bAddr[p] + off);
    };

    int s_cur = 0;
    for (int kt = 0; kt < KT; kt++) {
        int s_next = (s_cur + 1 == STAGES) ? 0 : s_cur + 1;
        int s_load = (s_next + 1 == STAGES) ? 0 : s_next + 1;
        if (kt + STAGES - 1 < KT) load_stage(kt + STAGES - 1, s_load);
        CP_COMMIT();

#pragma unroll
        for (int ks = 0; ks < 4; ks++) {
            frag_load(s_cur, ks);
#pragma unroll
            for (int mt = 0; mt < 4; mt++)
#pragma unroll
                for (int nt = 0; nt < 8; nt++)
                    mma_tf32(acc[mt][nt], af[mt][0], af[mt][1], af[mt][2], af[mt][3],
                             bf[nt][0], bf[nt][1]);
        }

        if (kt + 1 < KT) {
            CP_WAIT(STAGES - 2);
            __syncthreads();
        }
        s_cur = s_next;
    }

    // epilogue: warp covers rows [wm*64, +64), cols [wn*64, +64)
#pragma unroll
    for (int mt = 0; mt < 4; mt++) {
#pragma unroll
        for (int half = 0; half < 2; half++) {
            int row = bm + wm * 64 + mt * 16 + r + half * 8;
#pragma unroll
            for (int nt = 0; nt < 8; nt++) {
                int col = bn + wn * 64 + nt * 8 + 2 * c;
                float v0 = acc[mt][nt][half * 2 + 0];
                float v1 = acc[mt][nt][half * 2 + 1];
                size_t off = (size_t)row * N + col;
                if (BIAS) { v0 += bias[col]; v1 += bias[col + 1]; }
                if (GELU) {
                    const float kk = 0.70710678118654752440f;
                    v0 = 0.5f * v0 * (1.f + erff(v0 * kk));
                    v1 = 0.5f * v1 * (1.f + erff(v1 * kk));
                }
                if (RES) {
                    float2 rr = *(const float2*)(resid + off);
                    v0 += rr.x; v1 += rr.y;
                }
                if (ROUND) { v0 = f2tf32f(v0); v1 = f2tf32f(v1); }
                *(float2*)(C + off) = make_float2(v0, v1);
            }
        }
    }
}

// ---------------- TF32 MMA flash attention: ldmatrix frags + cp.async K/V ----------------
#define AROW 68
#define ATTN_SMEM_BYTES (4 * 64 * AROW * 4)

__global__ void __launch_bounds__(128, 3)
attn_mma(const float* __restrict__ QKV, float* __restrict__ Og) {
    extern __shared__ float sm[];
    float* Qs = sm;
    float* Ks = Qs + 64 * AROW;
    float* Vs = Ks + 64 * AROW;
    float* Ps = Vs + 64 * AROW;

    int tid  = threadIdx.x;
    int lane = tid & 31;
    int w    = tid >> 5;
    int r    = lane >> 2;
    int c    = lane & 3;
    int l8   = lane & 7;
    int lhi  = (lane >> 3) & 1;
    int lc4  = (lane >> 4) & 1;

    int qt = blockIdx.x;
    int h  = blockIdx.y;
    int b  = blockIdx.z;
    size_t qbase = (size_t)b * S_ * QKVN + (size_t)h * HD_;
    const float* Qg = QKV + qbase;
    const float* Kg = QKV + qbase + D_;
    const float* Vg = QKV + qbase + 2 * D_;
    size_t obase = (size_t)b * S_ * D_ + (size_t)h * HD_;
    int q0 = qt * 64;

    uint32_t sbase = smem_u32(sm);
    uint32_t qAddr = sbase + (uint32_t)((16 * w + l8 + lhi * 8) * AROW + lc4 * 4) * 4;
    uint32_t pAddr = sbase + (uint32_t)(3 * 64 * AROW + (16 * w + l8 + lhi * 8) * AROW + lc4 * 4) * 4;
    uint32_t kAddr[4];
#pragma unroll
    for (int p = 0; p < 4; p++)
        kAddr[p] = sbase + (uint32_t)(64 * AROW + (p * 16 + l8 + lhi * 8) * AROW + lc4 * 4) * 4;

    auto load_K = [&](int kt) {
#pragma unroll
        for (int i = 0; i < 8; i++) {
            int j   = tid + 128 * i;
            int row = j >> 4;
            int c4  = (j & 15) * 4;
            CP_ASYNC16(smem_u32(&Ks[row * AROW + c4]),
                       &Kg[(size_t)(kt * 64 + row) * QKVN + c4]);
        }
        CP_COMMIT();
    };
    auto load_V = [&](int kt) {
#pragma unroll
        for (int i = 0; i < 8; i++) {
            int j   = tid + 128 * i;
            int row = j >> 4;
            int c4  = (j & 15) * 4;
            CP_ASYNC16(smem_u32(&Vs[row * AROW + c4]),
                       &Vg[(size_t)(kt * 64 + row) * QKVN + c4]);
        }
        CP_COMMIT();
    };

    load_K(0);
    load_V(0);
#pragma unroll
    for (int i = 0; i < 8; i++) {
        int j   = tid + 128 * i;
        int row = j >> 4;
        int c4  = (j & 15) * 4;
        float4 v = *(const float4*)&Qg[(size_t)(q0 + row) * QKVN + c4];
        v.x *= 0.125f; v.y *= 0.125f; v.z *= 0.125f; v.w *= 0.125f;
        *(float4*)&Qs[row * AROW + c4] = v;
    }
    __syncthreads();

    unsigned qf[8][4];
#pragma unroll
    for (int ks = 0; ks < 8; ks++)
        LDSM4(qf[ks][0], qf[ks][1], qf[ks][2], qf[ks][3], qAddr + ks * 32);

    float m0 = -1e30f, m8 = -1e30f, l0 = 0.f, l8sum = 0.f;
    float oacc[8][4];
#pragma unroll
    for (int nt = 0; nt < 8; nt++)
#pragma unroll
        for (int t = 0; t < 4; t++) oacc[nt][t] = 0.f;

    int qrow  = 16 * w + r;
    float* PsA = &Ps[qrow * AROW];

    const int KT = S_ / 64;
    for (int kt = 0; kt < KT; kt++) {
        CP_WAIT(1);
        __syncthreads();

        float sacc[8][4];
#pragma unroll
        for (int nt = 0; nt < 8; nt++)
#pragma unroll
            for (int t = 0; t < 4; t++) sacc[nt][t] = 0.f;

        unsigned kf[2][8][2];
#pragma unroll
        for (int p = 0; p < 4; p++)
            LDSM4(kf[0][2 * p][0], kf[0][2 * p + 1][0],
                  kf[0][2 * p][1], kf[0][2 * p + 1][1], kAddr[p]);
#pragma unroll
        for (int ks = 0; ks < 8; ks++) {
            int buf = ks & 1;
            if (ks < 7) {
                uint32_t off = (uint32_t)(ks + 1) * 32;
#pragma unroll
                for (int p = 0; p < 4; p++)
                    LDSM4(kf[buf ^ 1][2 * p][0], kf[buf ^ 1][2 * p + 1][0],
                          kf[buf ^ 1][2 * p][1], kf[buf ^ 1][2 * p + 1][1],
                          kAddr[p] + off);
            }
#pragma unroll
            for (int nt = 0; nt < 8; nt++)
                mma_tf32(sacc[nt], qf[ks][0], qf[ks][1], qf[ks][2], qf[ks][3],
                         kf[buf][nt][0], kf[buf][nt][1]);
        }

        __syncthreads();
        if (kt + 1 < KT) load_K(kt + 1);

        float mx0 = -1e30f, mx8 = -1e30f;
#pragma unroll
        for (int nt = 0; nt < 8; nt++) {
            mx0 = fmaxf(mx0, fmaxf(sacc[nt][0], sacc[nt][1]));
            mx8 = fmaxf(mx8, fmaxf(sacc[nt][2], sacc[nt][3]));
        }
        mx0 = fmaxf(mx0, __shfl_xor_sync(0xffffffffu, mx0, 1));
        mx0 = fmaxf(mx0, __shfl_xor_sync(0xffffffffu, mx0, 2));
        mx8 = fmaxf(mx8, __shfl_xor_sync(0xffffffffu, mx8, 1));
        mx8 = fmaxf(mx8, __shfl_xor_sync(0xffffffffu, mx8, 2));

        float mn0 = fmaxf(m0, mx0);
        float mn8 = fmaxf(m8, mx8);
        float cor0 = __expf(m0 - mn0);
        float cor8 = __expf(m8 - mn8);
        float s0 = 0.f, s8 = 0.f;
#pragma unroll
        for (int nt = 0; nt < 8; nt++) {
            float e0 = __expf(sacc[nt][0] - mn0);
            float e1 = __expf(sacc[nt][1] - mn0);
            float e2 = __expf(sacc[nt][2] - mn8);
            float e3 = __expf(sacc[nt][3] - mn8);
            s0 += e0 + e1;
            s8 += e2 + e3;
            *(float2*)&PsA[8 * nt + 2 * c]            = make_float2(f2tf32f(e0), f2tf32f(e1));
            *(float2*)&PsA[8 * AROW + 8 * nt + 2 * c] = make_float2(f2tf32f(e2), f2tf32f(e3));
        }
        s0 += __shfl_xor_sync(0xffffffffu, s0, 1);
        s0 += __shfl_xor_sync(0xffffffffu, s0, 2);
        s8 += __shfl_xor_sync(0xffffffffu, s8, 1);
        s8 += __shfl_xor_sync(0xffffffffu, s8, 2);

        l0    = l0 * cor0 + s0;
        l8sum = l8sum * cor8 + s8;
        m0 = mn0;
        m8 = mn8;

#pragma unroll
        for (int nt = 0; nt < 8; nt++) {
            oacc[nt][0] *= cor0; oacc[nt][1] *= cor0;
            oacc[nt][2] *= cor8; oacc[nt][3] *= cor8;
        }

        if (kt + 1 < KT) { CP_WAIT(1); } else { CP_WAIT(0); }
        __syncthreads();

#pragma unroll
        for (int ks = 0; ks < 8; ks++) {
            int kk = ks * 8;
            unsigned pf0, pf1, pf2, pf3;
            LDSM4(pf0, pf1, pf2, pf3, pAddr + (uint32_t)ks * 32);
#pragma unroll
            for (int nt = 0; nt < 8; nt++) {
                unsigned b0 = __float_as_uint(Vs[(kk + c) * AROW + 8 * nt + r]);
                unsigned b1 = __float_as_uint(Vs[(kk + c + 4) * AROW + 8 * nt + r]);
                mma_tf32(oacc[nt], pf0, pf1, pf2, pf3, b0, b1);
            }
        }

        __syncthreads();
        if (kt + 1 < KT) load_V(kt + 1);
    }

    float inv0 = 1.f / l0;
    float inv8 = 1.f / l8sum;
    size_t row0 = obase + (size_t)(q0 + qrow) * D_;
    size_t row8 = row0 + (size_t)8 * D_;
#pragma unroll
    for (int nt = 0; nt < 8; nt++) {
        int col = 8 * nt + 2 * c;
        *(float2*)&Og[row0 + col] =
            make_float2(f2tf32f(oacc[nt][0] * inv0), f2tf32f(oacc[nt][1] * inv0));
        *(float2*)&Og[row8 + col] =
            make_float2(f2tf32f(oacc[nt][2] * inv8), f2tf32f(oacc[nt][3] * inv8));
    }
}

// ---------------- launch ----------------
extern "C" void kernel_launch(void* const* d_in, const int* in_sizes, int n_in,
                              void* d_out, int out_size) {
    const float* x     = (const float*)d_in[0];
    const float* ln1_g = (const float*)d_in[2];
    const float* ln1_b = (const float*)d_in[3];
    const float* wq    = (const float*)d_in[4];
    const float* wk    = (const float*)d_in[5];
    const float* wv    = (const float*)d_in[6];
    const float* wo    = (const float*)d_in[7];
    const float* bo    = (const float*)d_in[8];
    const float* ln2_g = (const float*)d_in[9];
    const float* ln2_b = (const float*)d_in[10];
    const float* w1    = (const float*)d_in[11];
    const float* b1    = (const float*)d_in[12];
    const float* w2    = (const float*)d_in[13];
    const float* b2    = (const float*)d_in[14];
    float* out = (float*)d_out;

    float *lnb, *qkv, *attn, *hbuf, *wqkvT, *woT, *w1T, *w2T;
    cudaGetSymbolAddress((void**)&lnb,   g_ln);
    cudaGetSymbolAddress((void**)&qkv,   g_qkv);
    cudaGetSymbolAddress((void**)&attn,  g_attn);
    cudaGetSymbolAddress((void**)&hbuf,  g_h);
    cudaGetSymbolAddress((void**)&wqkvT, g_wqkvT);
    cudaGetSymbolAddress((void**)&woT,   g_woT);
    cudaGetSymbolAddress((void**)&w1T,   g_w1T);
    cudaGetSymbolAddress((void**)&w2T,   g_w2T);

    cudaFuncSetAttribute(attn_mma, cudaFuncAttributeMaxDynamicSharedMemorySize, ATTN_SMEM_BYTES);
    cudaFuncSetAttribute(tgemm<false, false, false, true>,  cudaFuncAttributeMaxDynamicSharedMemorySize, TG_SMEM_BYTES);
    cudaFuncSetAttribute(tgemm<true, false, true, false>,   cudaFuncAttributeMaxDynamicSharedMemorySize, TG_SMEM_BYTES);
    cudaFuncSetAttribute(tgemm<true, true, false, true>,    cudaFuncAttributeMaxDynamicSharedMemorySize, TG_SMEM_BYTES);

    // 0) transpose + round weights (QKV packed as [3072][1024])
    dim3 tb(32, 8);
    tround<<<dim3(D_ / 32, D_ / 32), tb>>>(wq, wqkvT,                 D_, D_);
    tround<<<dim3(D_ / 32, D_ / 32), tb>>>(wk, wqkvT + D_ * D_,       D_, D_);
    tround<<<dim3(D_ / 32, D_ / 32), tb>>>(wv, wqkvT + 2 * D_ * D_,   D_, D_);
    tround<<<dim3(D_ / 32, D_ / 32), tb>>>(wo, woT,                   D_, D_);
    tround<<<dim3(FF_ / 32, D_ / 32), tb>>>(w1, w1T, D_, FF_);
    tround<<<dim3(D_ / 32, FF_ / 32), tb>>>(w2, w2T, FF_, D_);

    // 1) LN1 (rounded output)
    ln_kernel<<<ROWS_, 256>>>(x, ln1_g, ln1_b, lnb);

    // 2) fused QKV projection
    dim3 gQKV(QKVN / 256, ROWS_ / 128);
    tgemm<false, false, false, true><<<gQKV, 256, TG_SMEM_BYTES>>>(
        lnb, wqkvT, qkv, nullptr, nullptr, ROWS_, QKVN, D_);

    // 3) attention
    attn_mma<<<dim3(S_ / 64, H_, B_), 128, ATTN_SMEM_BYTES>>>(qkv, attn);

    // 4) out proj + bias + residual(x)
    dim3 gD(D_ / 256, ROWS_ / 128);
    tgemm<true, false, true, false><<<gD, 256, TG_SMEM_BYTES>>>(
        attn, woT, out, bo, x, ROWS_, D_, D_);

    // 5) LN2 (rounded output)
    ln_kernel<<<ROWS_, 256>>>(out, ln2_g, ln2_b, lnb);

    // 6) MLP up + bias + exact gelu (rounded output)
    dim3 gF(FF_ / 256, ROWS_ / 128);
    tgemm<true, true, false, true><<<gF, 256, TG_SMEM_BYTES>>>(
        lnb, w1T, hbuf, b1, nullptr, ROWS_, FF_, D_);

    // 7) MLP down + bias + residual(out)
    tgemm<true, false, true, false><<<gD, 256, TG_SMEM_BYTES>>>(
        hbuf, w2T, out, b2, out, ROWS_, D_, FF_);
}

// round 17
// speedup vs baseline: 1.2159x; 1.2159x over previous
#include <cuda_runtime.h>
#include <math.h>
#include <cstdint>

#define B_ 4
#define S_ 2048
#define D_ 1024
#define H_ 16
#define HD_ 64
#define FF_ 4096
#define ROWS_ (B_ * S_)   // 8192
#define QKVN 3072

// ---------------- scratch (device globals; no allocation) ----------------
__device__ float g_ln[ROWS_ * D_];
__device__ float g_qkv[(size_t)ROWS_ * QKVN];
__device__ float g_attn[ROWS_ * D_];
__device__ float g_h[(size_t)ROWS_ * FF_];
__device__ float g_wqkvT[QKVN * D_];   // transposed+rounded [n][k]
__device__ float g_woT[D_ * D_];
__device__ float g_w1T[FF_ * D_];
__device__ float g_w2T[D_ * FF_];

// ---------------- helpers ----------------
__device__ __forceinline__ uint32_t smem_u32(const void* p) {
    uint32_t a;
    asm("{ .reg .u64 t; cvta.to.shared.u64 t, %1; cvt.u32.u64 %0, t; }" : "=r"(a) : "l"(p));
    return a;
}
#define CP_ASYNC16(dst, src) \
    asm volatile("cp.async.cg.shared.global [%0], [%1], 16;" :: "r"(dst), "l"(src))
#define CP_COMMIT() asm volatile("cp.async.commit_group;" ::: "memory")
#define CP_WAIT(n)  asm volatile("cp.async.wait_group %0;" :: "n"(n) : "memory")
#define LDSM4(r0, r1, r2, r3, addr) \
    asm volatile("ldmatrix.sync.aligned.m8n8.x4.shared.b16 {%0,%1,%2,%3}, [%4];" \
                 : "=r"(r0), "=r"(r1), "=r"(r2), "=r"(r3) : "r"(addr))

__device__ __forceinline__ unsigned f2tf32(float f) {
    unsigned u;
    asm("cvt.rna.tf32.f32 %0, %1;" : "=r"(u) : "f"(f));
    return u;
}
__device__ __forceinline__ float f2tf32f(float f) { return __uint_as_float(f2tf32(f)); }

__device__ __forceinline__ void mma_tf32(float c[4], unsigned a0, unsigned a1,
                                         unsigned a2, unsigned a3,
                                         unsigned b0, unsigned b1) {
    asm volatile(
        "mma.sync.aligned.m16n8k8.row.col.f32.tf32.tf32.f32 "
        "{%0,%1,%2,%3}, {%4,%5,%6,%7}, {%8,%9}, {%0,%1,%2,%3};"
        : "+f"(c[0]), "+f"(c[1]), "+f"(c[2]), "+f"(c[3])
        : "r"(a0), "r"(a1), "r"(a2), "r"(a3), "r"(b0), "r"(b1));
}

// ---------------- weight transpose + tf32 round: out[n][k] = rna(in[k][n]) ----------------
__global__ void tround(const float* __restrict__ in, float* __restrict__ out,
                       int K, int N) {
    __shared__ float t[32][33];
    int n0 = blockIdx.x * 32, k0 = blockIdx.y * 32;
    int tx = threadIdx.x, ty = threadIdx.y;    // 32 x 8
#pragma unroll
    for (int i = 0; i < 4; i++)
        t[ty + 8 * i][tx] = in[(size_t)(k0 + ty + 8 * i) * N + n0 + tx];
    __syncthreads();
#pragma unroll
    for (int i = 0; i < 4; i++)
        out[(size_t)(n0 + ty + 8 * i) * K + k0 + tx] = f2tf32f(t[tx][ty + 8 * i]);
}

// ---------------- LayerNorm (output rounded to tf32) ----------------
__global__ void ln_kernel(const float* __restrict__ x, const float* __restrict__ g,
                          const float* __restrict__ b, float* __restrict__ y) {
    int row = blockIdx.x;
    int tid = threadIdx.x;
    const float4* xr = (const float4*)(x + (size_t)row * D_);
    float4 v = xr[tid];
    float s  = v.x + v.y + v.z + v.w;
    float ss = fmaf(v.x, v.x, fmaf(v.y, v.y, fmaf(v.z, v.z, v.w * v.w)));
#pragma unroll
    for (int o = 16; o > 0; o >>= 1) {
        s  += __shfl_xor_sync(0xffffffffu, s,  o);
        ss += __shfl_xor_sync(0xffffffffu, ss, o);
    }
    __shared__ float smS[8], smSS[8];
    __shared__ float mean_s, rstd_s;
    int wid = tid >> 5, lane = tid & 31;
    if (lane == 0) { smS[wid] = s; smSS[wid] = ss; }
    __syncthreads();
    if (tid == 0) {
        float S = 0.f, SQ = 0.f;
#pragma unroll
        for (int i = 0; i < 8; i++) { S += smS[i]; SQ += smSS[i]; }
        float m = S * (1.0f / D_);
        float var = SQ * (1.0f / D_) - m * m;
        mean_s = m;
        rstd_s = rsqrtf(var + 1e-5f);
    }
    __syncthreads();
    float m = mean_s, rs = rstd_s;
    float4 g4 = ((const float4*)g)[tid];
    float4 b4 = ((const float4*)b)[tid];
    float4 o;
    o.x = f2tf32f((v.x - m) * rs * g4.x + b4.x);
    o.y = f2tf32f((v.y - m) * rs * g4.y + b4.y);
    o.z = f2tf32f((v.z - m) * rs * g4.z + b4.z);
    o.w = f2tf32f((v.w - m) * rs * g4.w + b4.w);
    ((float4*)(y + (size_t)row * D_))[tid] = o;
}

// ---------------- TF32 tensor GEMM (R15 config): ldmatrix frags, 3-stage cp.async ----------------
#define STAGES 3
#define KS 32
#define ASTRIDE 36
#define A_STG (128 * ASTRIDE)
#define B_STG (128 * ASTRIDE)
#define STG_FLOATS (A_STG + B_STG)              // 9216
#define STG_BYTES (STG_FLOATS * 4)              // 36864
#define TG_SMEM_BYTES (STAGES * STG_BYTES)      // 110592

template <bool BIAS, bool GELU, bool RES, bool ROUND>
__global__ void __launch_bounds__(256, 2)
tgemm(const float* __restrict__ A, const float* __restrict__ Wt,
      float* __restrict__ C, const float* __restrict__ bias,
      const float* __restrict__ resid, int M, int N, int K) {
    extern __shared__ float sm[];
    int tid  = threadIdx.x;
    int lane = tid & 31;
    int wid  = tid >> 5;
    int wm   = wid >> 2;
    int wn   = wid & 3;
    int bm   = blockIdx.y * 128;
    int bn   = blockIdx.x * 128;
    int r    = lane >> 2;
    int c    = lane & 3;

    const int KT = K / KS;
    uint32_t sbase = smem_u32(sm);

    int l8  = lane & 7;
    int lhi = (lane >> 3) & 1;
    int lc4 = (lane >> 4) & 1;
    uint32_t aAddr[4], bAddr[2];
#pragma unroll
    for (int mt = 0; mt < 4; mt++) {
        int row = wm * 64 + mt * 16 + l8 + lhi * 8;
        aAddr[mt] = sbase + (uint32_t)(row * ASTRIDE + lc4 * 4) * 4;
    }
#pragma unroll
    for (int p = 0; p < 2; p++) {
        int row = wn * 32 + p * 16 + l8 + lhi * 8;
        bAddr[p] = sbase + (uint32_t)(A_STG + row * ASTRIDE + lc4 * 4) * 4;
    }

    auto load_stage = [&](int kt, int s) {
        float* sa = sm + s * STG_FLOATS;
        float* sb = sa + A_STG;
        const float* Ag = A  + (size_t)bm * K + kt * KS;
        const float* Bg = Wt + (size_t)bn * K + kt * KS;
#pragma unroll
        for (int i = 0; i < 4; i++) {
            int j = tid + 256 * i;
            int row = j >> 3, ch = j & 7;
            CP_ASYNC16(smem_u32(&sa[row * ASTRIDE + ch * 4]),
                       Ag + (size_t)row * K + ch * 4);
        }
#pragma unroll
        for (int i = 0; i < 4; i++) {
            int j = tid + 256 * i;
            int row = j >> 3, ch = j & 7;
            CP_ASYNC16(smem_u32(&sb[row * ASTRIDE + ch * 4]),
                       Bg + (size_t)row * K + ch * 4);
        }
    };

    float acc[4][4][4];
#pragma unroll
    for (int i = 0; i < 4; i++)
#pragma unroll
        for (int j = 0; j < 4; j++)
#pragma unroll
            for (int t = 0; t < 4; t++) acc[i][j][t] = 0.f;

#pragma unroll
    for (int s = 0; s < STAGES - 1; s++) {
        load_stage(s, s);
        CP_COMMIT();
    }
    CP_WAIT(STAGES - 2);
    __syncthreads();

    unsigned af[2][4][4], bf[2][4][2];
    auto frag_load = [&](int s, int ks, int buf) {
        uint32_t off = (uint32_t)s * STG_BYTES + (uint32_t)ks * 32;
#pragma unroll
        for (int mt = 0; mt < 4; mt++)
            LDSM4(af[buf][mt][0], af[buf][mt][1], af[buf][mt][2], af[buf][mt][3],
                  aAddr[mt] + off);
#pragma unroll
        for (int p = 0; p < 2; p++)
            LDSM4(bf[buf][2 * p][0], bf[buf][2 * p + 1][0],
                  bf[buf][2 * p][1], bf[buf][2 * p + 1][1],
                  bAddr[p] + off);
    };

    frag_load(0, 0, 0);

    int s_cur = 0;
    for (int kt = 0; kt < KT; kt++) {
        int s_next = (s_cur + 1 == STAGES) ? 0 : s_cur + 1;
        int s_load = (s_next + 1 == STAGES) ? 0 : s_next + 1;
        if (kt + STAGES - 1 < KT) load_stage(kt + STAGES - 1, s_load);
        CP_COMMIT();

#pragma unroll
        for (int ks = 0; ks < 4; ks++) {
            int buf = ks & 1;
            if (ks < 3) {
                frag_load(s_cur, ks + 1, buf ^ 1);
            } else if (kt + 1 < KT) {
                CP_WAIT(STAGES - 2);
                __syncthreads();
                frag_load(s_next, 0, buf ^ 1);
            }
#pragma unroll
            for (int mt = 0; mt < 4; mt++)
#pragma unroll
                for (int nt = 0; nt < 4; nt++)
                    mma_tf32(acc[mt][nt], af[buf][mt][0], af[buf][mt][1],
                             af[buf][mt][2], af[buf][mt][3],
                             bf[buf][nt][0], bf[buf][nt][1]);
        }
        s_cur = s_next;
    }

    // epilogue
#pragma unroll
    for (int mt = 0; mt < 4; mt++) {
#pragma unroll
        for (int half = 0; half < 2; half++) {
            int row = bm + wm * 64 + mt * 16 + r + half * 8;
#pragma unroll
            for (int nt = 0; nt < 4; nt++) {
                int col = bn + wn * 32 + nt * 8 + 2 * c;
                float v0 = acc[mt][nt][half * 2 + 0];
                float v1 = acc[mt][nt][half * 2 + 1];
                size_t off = (size_t)row * N + col;
                if (BIAS) { v0 += bias[col]; v1 += bias[col + 1]; }
                if (GELU) {
                    const float kk = 0.70710678118654752440f;
                    v0 = 0.5f * v0 * (1.f + erff(v0 * kk));
                    v1 = 0.5f * v1 * (1.f + erff(v1 * kk));
                }
                if (RES) {
                    float2 rr = *(const float2*)(resid + off);
                    v0 += rr.x; v1 += rr.y;
                }
                if (ROUND) { v0 = f2tf32f(v0); v1 = f2tf32f(v1); }
                *(float2*)(C + off) = make_float2(v0, v1);
            }
        }
    }
}

// ---------------- TF32 MMA flash attention: Bq=128, 256 thr, ldmatrix + cp.async ----------------
#define AROW 68
#define ATTN_SMEM_BYTES ((128 + 64 + 64 + 128) * AROW * 4)   // 104448

__global__ void __launch_bounds__(256, 2)
attn_mma(const float* __restrict__ QKV, float* __restrict__ Og) {
    extern __shared__ float sm[];
    float* Qs = sm;                   // [128][AROW]
    float* Ks = Qs + 128 * AROW;      // [64][AROW]
    float* Vs = Ks + 64 * AROW;       // [64][AROW]
    float* Ps = Vs + 64 * AROW;       // [128][AROW]

    int tid  = threadIdx.x;
    int lane = tid & 31;
    int w    = tid >> 5;              // 0..7
    int r    = lane >> 2;
    int c    = lane & 3;
    int l8   = lane & 7;
    int lhi  = (lane >> 3) & 1;
    int lc4  = (lane >> 4) & 1;

    int qt = blockIdx.x;              // 0..15 (128-row q tiles)
    int h  = blockIdx.y;
    int b  = blockIdx.z;
    size_t qbase = (size_t)b * S_ * QKVN + (size_t)h * HD_;
    const float* Qg = QKV + qbase;
    const float* Kg = QKV + qbase + D_;
    const float* Vg = QKV + qbase + 2 * D_;
    size_t obase = (size_t)b * S_ * D_ + (size_t)h * HD_;
    int q0 = qt * 128;

    uint32_t sbase = smem_u32(sm);
    uint32_t qAddr = sbase + (uint32_t)((16 * w + l8 + lhi * 8) * AROW + lc4 * 4) * 4;
    uint32_t pAddr = sbase + (uint32_t)(256 * AROW + (16 * w + l8 + lhi * 8) * AROW + lc4 * 4) * 4;
    uint32_t kAddr[4];
#pragma unroll
    for (int p = 0; p < 4; p++)
        kAddr[p] = sbase + (uint32_t)(128 * AROW + (p * 16 + l8 + lhi * 8) * AROW + lc4 * 4) * 4;

    auto load_K = [&](int kt) {
#pragma unroll
        for (int i = 0; i < 4; i++) {
            int j   = tid + 256 * i;       // 0..1023
            int row = j >> 4;
            int c4  = (j & 15) * 4;
            CP_ASYNC16(smem_u32(&Ks[row * AROW + c4]),
                       &Kg[(size_t)(kt * 64 + row) * QKVN + c4]);
        }
        CP_COMMIT();
    };
    auto load_V = [&](int kt) {
#pragma unroll
        for (int i = 0; i < 4; i++) {
            int j   = tid + 256 * i;
            int row = j >> 4;
            int c4  = (j & 15) * 4;
            CP_ASYNC16(smem_u32(&Vs[row * AROW + c4]),
                       &Vg[(size_t)(kt * 64 + row) * QKVN + c4]);
        }
        CP_COMMIT();
    };

    load_K(0);
    load_V(0);
    // Q tile [128][64], pre-rounded; x0.125 exact
#pragma unroll
    for (int i = 0; i < 8; i++) {
        int j   = tid + 256 * i;           // 0..2047
        int row = j >> 4;
        int c4  = (j & 15) * 4;
        float4 v = *(const float4*)&Qg[(size_t)(q0 + row) * QKVN + c4];
        v.x *= 0.125f; v.y *= 0.125f; v.z *= 0.125f; v.w *= 0.125f;
        *(float4*)&Qs[row * AROW + c4] = v;
    }
    __syncthreads();

    unsigned qf[8][4];
#pragma unroll
    for (int ks = 0; ks < 8; ks++)
        LDSM4(qf[ks][0], qf[ks][1], qf[ks][2], qf[ks][3], qAddr + ks * 32);

    float m0 = -1e30f, m8 = -1e30f, l0 = 0.f, l8sum = 0.f;
    float oacc[8][4];
#pragma unroll
    for (int nt = 0; nt < 8; nt++)
#pragma unroll
        for (int t = 0; t < 4; t++) oacc[nt][t] = 0.f;

    int qrow  = 16 * w + r;
    float* PsA = &Ps[qrow * AROW];

    const int KT = S_ / 64;
    for (int kt = 0; kt < KT; kt++) {
        CP_WAIT(1);
        __syncthreads();

        float sacc[8][4];
#pragma unroll
        for (int nt = 0; nt < 8; nt++)
#pragma unroll
            for (int t = 0; t < 4; t++) sacc[nt][t] = 0.f;

        unsigned kf[2][8][2];
#pragma unroll
        for (int p = 0; p < 4; p++)
            LDSM4(kf[0][2 * p][0], kf[0][2 * p + 1][0],
                  kf[0][2 * p][1], kf[0][2 * p + 1][1], kAddr[p]);
#pragma unroll
        for (int ks = 0; ks < 8; ks++) {
            int buf = ks & 1;
            if (ks < 7) {
                uint32_t off = (uint32_t)(ks + 1) * 32;
#pragma unroll
                for (int p = 0; p < 4; p++)
                    LDSM4(kf[buf ^ 1][2 * p][0], kf[buf ^ 1][2 * p + 1][0],
                          kf[buf ^ 1][2 * p][1], kf[buf ^ 1][2 * p + 1][1],
                          kAddr[p] + off);
            }
#pragma unroll
            for (int nt = 0; nt < 8; nt++)
                mma_tf32(sacc[nt], qf[ks][0], qf[ks][1], qf[ks][2], qf[ks][3],
                         kf[buf][nt][0], kf[buf][nt][1]);
        }

        __syncthreads();
        if (kt + 1 < KT) load_K(kt + 1);

        float mx0 = -1e30f, mx8 = -1e30f;
#pragma unroll
        for (int nt = 0; nt < 8; nt++) {
            mx0 = fmaxf(mx0, fmaxf(sacc[nt][0], sacc[nt][1]));
            mx8 = fmaxf(mx8, fmaxf(sacc[nt][2], sacc[nt][3]));
        }
        mx0 = fmaxf(mx0, __shfl_xor_sync(0xffffffffu, mx0, 1));
        mx0 = fmaxf(mx0, __shfl_xor_sync(0xffffffffu, mx0, 2));
        mx8 = fmaxf(mx8, __shfl_xor_sync(0xffffffffu, mx8, 1));
        mx8 = fmaxf(mx8, __shfl_xor_sync(0xffffffffu, mx8, 2));

        float mn0 = fmaxf(m0, mx0);
        float mn8 = fmaxf(m8, mx8);
        float cor0 = __expf(m0 - mn0);
        float cor8 = __expf(m8 - mn8);
        float s0 = 0.f, s8 = 0.f;
#pragma unroll
        for (int nt = 0; nt < 8; nt++) {
            float e0 = __expf(sacc[nt][0] - mn0);
            float e1 = __expf(sacc[nt][1] - mn0);
            float e2 = __expf(sacc[nt][2] - mn8);
            float e3 = __expf(sacc[nt][3] - mn8);
            s0 += e0 + e1;
            s8 += e2 + e3;
            *(float2*)&PsA[8 * nt + 2 * c]            = make_float2(f2tf32f(e0), f2tf32f(e1));
            *(float2*)&PsA[8 * AROW + 8 * nt + 2 * c] = make_float2(f2tf32f(e2), f2tf32f(e3));
        }
        s0 += __shfl_xor_sync(0xffffffffu, s0, 1);
        s0 += __shfl_xor_sync(0xffffffffu, s0, 2);
        s8 += __shfl_xor_sync(0xffffffffu, s8, 1);
        s8 += __shfl_xor_sync(0xffffffffu, s8, 2);

        l0    = l0 * cor0 + s0;
        l8sum = l8sum * cor8 + s8;
        m0 = mn0;
        m8 = mn8;

#pragma unroll
        for (int nt = 0; nt < 8; nt++) {
            oacc[nt][0] *= cor0; oacc[nt][1] *= cor0;
            oacc[nt][2] *= cor8; oacc[nt][3] *= cor8;
        }

        if (kt + 1 < KT) { CP_WAIT(1); } else { CP_WAIT(0); }
        __syncthreads();

#pragma unroll
        for (int ks = 0; ks < 8; ks++) {
            int kk = ks * 8;
            unsigned pf0, pf1, pf2, pf3;
            LDSM4(pf0, pf1, pf2, pf3, pAddr + (uint32_t)ks * 32);
#pragma unroll
            for (int nt = 0; nt < 8; nt++) {
                unsigned b0 = __float_as_uint(Vs[(kk + c) * AROW + 8 * nt + r]);
                unsigned b1 = __float_as_uint(Vs[(kk + c + 4) * AROW + 8 * nt + r]);
                mma_tf32(oacc[nt], pf0, pf1, pf2, pf3, b0, b1);
            }
        }

        __syncthreads();
        if (kt + 1 < KT) load_V(kt + 1);
    }

    float inv0 = 1.f / l0;
    float inv8 = 1.f / l8sum;
    size_t row0 = obase + (size_t)(q0 + qrow) * D_;
    size_t row8 = row0 + (size_t)8 * D_;
#pragma unroll
    for (int nt = 0; nt < 8; nt++) {
        int col = 8 * nt + 2 * c;
        *(float2*)&Og[row0 + col] =
            make_float2(f2tf32f(oacc[nt][0] * inv0), f2tf32f(oacc[nt][1] * inv0));
        *(float2*)&Og[row8 + col] =
            make_float2(f2tf32f(oacc[nt][2] * inv8), f2tf32f(oacc[nt][3] * inv8));
    }
}

// ---------------- launch ----------------
extern "C" void kernel_launch(void* const* d_in, const int* in_sizes, int n_in,
                              void* d_out, int out_size) {
    const float* x     = (const float*)d_in[0];
    const float* ln1_g = (const float*)d_in[2];
    const float* ln1_b = (const float*)d_in[3];
    const float* wq    = (const float*)d_in[4];
    const float* wk    = (const float*)d_in[5];
    const float* wv    = (const float*)d_in[6];
    const float* wo    = (const float*)d_in[7];
    const float* bo    = (const float*)d_in[8];
    const float* ln2_g = (const float*)d_in[9];
    const float* ln2_b = (const float*)d_in[10];
    const float* w1    = (const float*)d_in[11];
    const float* b1    = (const float*)d_in[12];
    const float* w2    = (const float*)d_in[13];
    const float* b2    = (const float*)d_in[14];
    float* out = (float*)d_out;

    float *lnb, *qkv, *attn, *hbuf, *wqkvT, *woT, *w1T, *w2T;
    cudaGetSymbolAddress((void**)&lnb,   g_ln);
    cudaGetSymbolAddress((void**)&qkv,   g_qkv);
    cudaGetSymbolAddress((void**)&attn,  g_attn);
    cudaGetSymbolAddress((void**)&hbuf,  g_h);
    cudaGetSymbolAddress((void**)&wqkvT, g_wqkvT);
    cudaGetSymbolAddress((void**)&woT,   g_woT);
    cudaGetSymbolAddress((void**)&w1T,   g_w1T);
    cudaGetSymbolAddress((void**)&w2T,   g_w2T);

    cudaFuncSetAttribute(attn_mma, cudaFuncAttributeMaxDynamicSharedMemorySize, ATTN_SMEM_BYTES);
    cudaFuncSetAttribute(tgemm<false, false, false, true>,  cudaFuncAttributeMaxDynamicSharedMemorySize, TG_SMEM_BYTES);
    cudaFuncSetAttribute(tgemm<true, false, true, false>,   cudaFuncAttributeMaxDynamicSharedMemorySize, TG_SMEM_BYTES);
    cudaFuncSetAttribute(tgemm<true, true, false, true>,    cudaFuncAttributeMaxDynamicSharedMemorySize, TG_SMEM_BYTES);

    // 0) transpose + round weights (QKV packed as [3072][1024])
    dim3 tb(32, 8);
    tround<<<dim3(D_ / 32, D_ / 32), tb>>>(wq, wqkvT,                 D_, D_);
    tround<<<dim3(D_ / 32, D_ / 32), tb>>>(wk, wqkvT + D_ * D_,       D_, D_);
    tround<<<dim3(D_ / 32, D_ / 32), tb>>>(wv, wqkvT + 2 * D_ * D_,   D_, D_);
    tround<<<dim3(D_ / 32, D_ / 32), tb>>>(wo, woT,                   D_, D_);
    tround<<<dim3(FF_ / 32, D_ / 32), tb>>>(w1, w1T, D_, FF_);
    tround<<<dim3(D_ / 32, FF_ / 32), tb>>>(w2, w2T, FF_, D_);

    // 1) LN1 (rounded output)
    ln_kernel<<<ROWS_, 256>>>(x, ln1_g, ln1_b, lnb);

    // 2) fused QKV projection
    dim3 gQKV(QKVN / 128, ROWS_ / 128);
    tgemm<false, false, false, true><<<gQKV, 256, TG_SMEM_BYTES>>>(
        lnb, wqkvT, qkv, nullptr, nullptr, ROWS_, QKVN, D_);

    // 3) attention (Bq=128, 256 threads)
    attn_mma<<<dim3(S_ / 128, H_, B_), 256, ATTN_SMEM_BYTES>>>(qkv, attn);

    // 4) out proj + bias + residual(x)
    dim3 gD(D_ / 128, ROWS_ / 128);
    tgemm<true, false, true, false><<<gD, 256, TG_SMEM_BYTES>>>(
        attn, woT, out, bo, x, ROWS_, D_, D_);

    // 5) LN2 (rounded output)
    ln_kernel<<<ROWS_, 256>>>(out, ln2_g, ln2_b, lnb);

    // 6) MLP up + bias + exact gelu (rounded output)
    dim3 gF(FF_ / 128, ROWS_ / 128);
    tgemm<true, true, false, true><<<gF, 256, TG_SMEM_BYTES>>>(
        lnb, w1T, hbuf, b1, nullptr, ROWS_, FF_, D_);

    // 7) MLP down + bias + residual(out)
    tgemm<true, false, true, false><<<gD, 256, TG_SMEM_BYTES>>>(
        hbuf, w2T, out, b2, out, ROWS_, D_, FF_);
}